// round 2
// baseline (speedup 1.0000x reference)
#include <cuda_runtime.h>
#include <cuda_bf16.h>

#define N_NODES 50000
#define N_EDGES 800000
#define IN_DIM  256
#define HC      128   // HEADS * OUT_DIM
#define HEADS   4
#define NEG_SLOPE 0.2f
#define LN_EPS  1e-5f

// Scratch (static device globals; no allocation at runtime)
__device__ float g_h[(size_t)N_NODES * HC];      // transformed features [N,128]
__device__ float g_acc[(size_t)N_NODES * HC];    // weighted message accumulator
__device__ float g_as[N_NODES * HEADS];          // alpha_src per node/head
__device__ float g_ad[N_NODES * HEADS];          // alpha_dst per node/head
__device__ float g_denom[N_NODES * HEADS];       // softmax denominator

// ---------------------------------------------------------------------------
// K1: h = x @ W   (M=50000, K=256, N=128) fp32 tiled GEMM
// Block: 256 threads, computes 32 nodes x 128 cols.
// Thread (cg = tid&31, ng = tid>>5) computes 4 nodes x 4 cols.
// ---------------------------------------------------------------------------
__global__ __launch_bounds__(256) void gemm_k(const float* __restrict__ x,
                                              const float* __restrict__ W) {
    __shared__ float Ws[64 * HC];   // 32 KB: W[kb..kb+64, 0..128)
    __shared__ float Xs[32 * 64];   //  8 KB: x[tile nodes, kb..kb+64)

    const int tid = threadIdx.x;
    const int cg  = tid & 31;   // column group: cols 4*cg .. 4*cg+3
    const int ng  = tid >> 5;   // node group:   nodes 4*ng .. 4*ng+3 (in tile)
    const int nb  = blockIdx.x * 32;

    float acc[4][4];
#pragma unroll
    for (int j = 0; j < 4; j++)
#pragma unroll
        for (int c = 0; c < 4; c++) acc[j][c] = 0.f;

    for (int kb = 0; kb < IN_DIM; kb += 64) {
        // load W chunk: 64*128 floats = 2048 float4, 8 per thread
        const float4* Wg  = (const float4*)(W + (size_t)kb * HC);
        float4*       Wsv = (float4*)Ws;
#pragma unroll
        for (int i = 0; i < 8; i++) Wsv[tid + i * 256] = Wg[tid + i * 256];
        // load X tile: 32 nodes * 64 floats = 512 float4, 2 per thread
#pragma unroll
        for (int i = 0; i < 2; i++) {
            int idx = tid + i * 256;           // 0..511
            int n   = idx >> 4;                // node in tile
            int kk  = idx & 15;                // float4 index within 64 k's
            int gn  = nb + n; if (gn >= N_NODES) gn = N_NODES - 1;
            ((float4*)Xs)[idx] =
                *(const float4*)(x + (size_t)gn * IN_DIM + kb + kk * 4);
        }
        __syncthreads();
#pragma unroll
        for (int k = 0; k < 64; k++) {
            float4 w4 = ((const float4*)(Ws + k * HC))[cg];
#pragma unroll
            for (int j = 0; j < 4; j++) {
                float xv = Xs[(ng * 4 + j) * 64 + k];
                acc[j][0] = fmaf(xv, w4.x, acc[j][0]);
                acc[j][1] = fmaf(xv, w4.y, acc[j][1]);
                acc[j][2] = fmaf(xv, w4.z, acc[j][2]);
                acc[j][3] = fmaf(xv, w4.w, acc[j][3]);
            }
        }
        __syncthreads();
    }
#pragma unroll
    for (int j = 0; j < 4; j++) {
        int n = nb + ng * 4 + j;
        if (n < N_NODES)
            *(float4*)(g_h + (size_t)n * HC + cg * 4) =
                make_float4(acc[j][0], acc[j][1], acc[j][2], acc[j][3]);
    }
}

// ---------------------------------------------------------------------------
// K2: per-node: a_s, a_d (dot over 32 channels per head), plus self-loop init:
//     denom[n,h] = exp(leaky(a_s+a_d));  acc[n,:] = w_self * h[n,:]
// One warp per node. lane covers channels 4*lane..4*lane+3; head = lane>>3.
// ---------------------------------------------------------------------------
__global__ __launch_bounds__(256) void node_k(const float* __restrict__ att_src,
                                              const float* __restrict__ att_dst) {
    int gt   = blockIdx.x * 256 + threadIdx.x;
    int n    = gt >> 5;
    int lane = gt & 31;
    if (n >= N_NODES) return;

    float4 hv = *(const float4*)(g_h + (size_t)n * HC + lane * 4);
    float4 sv = *(const float4*)(att_src + lane * 4);
    float4 dv = *(const float4*)(att_dst + lane * 4);
    float ps = hv.x * sv.x + hv.y * sv.y + hv.z * sv.z + hv.w * sv.w;
    float pd = hv.x * dv.x + hv.y * dv.y + hv.z * dv.z + hv.w * dv.w;
    // reduce within each 8-lane group (one head = 32 channels = 8 lanes)
#pragma unroll
    for (int o = 4; o >= 1; o >>= 1) {
        ps += __shfl_xor_sync(0xffffffffu, ps, o, 8);
        pd += __shfl_xor_sync(0xffffffffu, pd, o, 8);
    }
    int head = lane >> 3;
    float z  = ps + pd;
    float e  = z > 0.f ? z : NEG_SLOPE * z;
    float w  = __expf(e);
    if ((lane & 7) == 0) {
        g_as[n * HEADS + head]    = ps;
        g_ad[n * HEADS + head]    = pd;
        g_denom[n * HEADS + head] = w;
    }
    *(float4*)(g_acc + (size_t)n * HC + lane * 4) =
        make_float4(w * hv.x, w * hv.y, w * hv.z, w * hv.w);
}

// ---------------------------------------------------------------------------
// K3: edge scatter. One warp per edge.
//   w = exp(leaky(a_s[src,h] + a_d[dst,h]))
//   denom[dst,h] += w ;  acc[dst, :] += w * h[src, :]
// Uses red.global.add.v4.f32 (sm_90+) for the 128-channel scatter.
// NOTE: edge_index arrives as int32 (JAX x64 disabled downcasts int64).
// ---------------------------------------------------------------------------
__global__ __launch_bounds__(256) void edge_k(const int* __restrict__ ei) {
    int gt   = blockIdx.x * 256 + threadIdx.x;
    int e    = gt >> 5;
    int lane = gt & 31;
    if (e >= N_EDGES) return;

    int s = __ldg(ei + e);
    int d = __ldg(ei + N_EDGES + e);

    float4 hv = __ldg((const float4*)(g_h + (size_t)s * HC) + lane);
    int head  = lane >> 3;
    float as  = __ldg(g_as + s * HEADS + head);
    float ad  = __ldg(g_ad + d * HEADS + head);
    float z   = as + ad;
    float le  = z > 0.f ? z : NEG_SLOPE * z;
    float w   = __expf(le);

    if ((lane & 7) == 0) atomicAdd(g_denom + d * HEADS + head, w);

    float* p = g_acc + (size_t)d * HC + lane * 4;
    asm volatile("red.global.add.v4.f32 [%0], {%1,%2,%3,%4};" ::
                 "l"(p), "f"(w * hv.x), "f"(w * hv.y),
                 "f"(w * hv.z), "f"(w * hv.w)
                 : "memory");
}

// ---------------------------------------------------------------------------
// K4: finalize: out = ELU( LN( acc/denom + bias ) * gamma + beta )
// One warp per node (128 channels, 4 per lane).
// ---------------------------------------------------------------------------
__global__ __launch_bounds__(256) void final_k(const float* __restrict__ bias,
                                               const float* __restrict__ gamma,
                                               const float* __restrict__ beta,
                                               float* __restrict__ out) {
    int gt   = blockIdx.x * 256 + threadIdx.x;
    int n    = gt >> 5;
    int lane = gt & 31;
    if (n >= N_NODES) return;

    float4 a  = *(const float4*)(g_acc + (size_t)n * HC + lane * 4);
    int head  = lane >> 3;
    float inv = 1.0f / g_denom[n * HEADS + head];
    float4 b4 = *(const float4*)(bias + lane * 4);

    float v0 = a.x * inv + b4.x;
    float v1 = a.y * inv + b4.y;
    float v2 = a.z * inv + b4.z;
    float v3 = a.w * inv + b4.w;

    float s = v0 + v1 + v2 + v3;
#pragma unroll
    for (int o = 16; o >= 1; o >>= 1) s += __shfl_xor_sync(0xffffffffu, s, o);
    float mean = s * (1.0f / 128.0f);

    float d0 = v0 - mean, d1 = v1 - mean, d2 = v2 - mean, d3 = v3 - mean;
    float q = d0 * d0 + d1 * d1 + d2 * d2 + d3 * d3;
#pragma unroll
    for (int o = 16; o >= 1; o >>= 1) q += __shfl_xor_sync(0xffffffffu, q, o);
    float r = rsqrtf(q * (1.0f / 128.0f) + LN_EPS);

    float4 g4  = *(const float4*)(gamma + lane * 4);
    float4 be4 = *(const float4*)(beta + lane * 4);
    float o0 = d0 * r * g4.x + be4.x;
    float o1 = d1 * r * g4.y + be4.y;
    float o2 = d2 * r * g4.z + be4.z;
    float o3 = d3 * r * g4.w + be4.w;
    // ELU (alpha = 1)
    o0 = o0 > 0.f ? o0 : (expf(o0) - 1.0f);
    o1 = o1 > 0.f ? o1 : (expf(o1) - 1.0f);
    o2 = o2 > 0.f ? o2 : (expf(o2) - 1.0f);
    o3 = o3 > 0.f ? o3 : (expf(o3) - 1.0f);

    *(float4*)(out + (size_t)n * HC + lane * 4) = make_float4(o0, o1, o2, o3);
}

// ---------------------------------------------------------------------------
extern "C" void kernel_launch(void* const* d_in, const int* in_sizes, int n_in,
                              void* d_out, int out_size) {
    const float* x       = (const float*)d_in[0];
    const int*   ei      = (const int*)d_in[1];
    const float* W       = (const float*)d_in[2];
    const float* att_src = (const float*)d_in[3];
    const float* att_dst = (const float*)d_in[4];
    const float* bias    = (const float*)d_in[5];
    const float* gamma   = (const float*)d_in[6];
    const float* beta    = (const float*)d_in[7];
    float*       out     = (float*)d_out;

    gemm_k<<<(N_NODES + 31) / 32, 256>>>(x, W);
    node_k<<<(N_NODES * 32 + 255) / 256, 256>>>(att_src, att_dst);
    edge_k<<<(N_EDGES + 7) / 8, 256>>>(ei);          // 1 warp / edge
    final_k<<<(N_NODES * 32 + 255) / 256, 256>>>(bias, gamma, beta, out);
}